// round 6
// baseline (speedup 1.0000x reference)
#include <cuda_runtime.h>
#include <math.h>

#define B_  8
#define T_  256
#define U_  64
#define U1_ 65
#define V_  512

#define ROWS (B_ * T_ * U1_)          // 133120
#define SM_STRIDE 66                   // padded row stride for conflict-free wavefront reads

// Scratch (allocation-free): blank/emit log-prob tables + per-batch partial losses.
__device__ float g_blank[ROWS];
__device__ float g_emit[ROWS];
__device__ float g_partial[B_];

// ---------------------------------------------------------------------------
// Kernel 1: per-row log-softmax, extracting only blank (v=0) and emit (v=tgt).
// One warp per (b,t,u) row of 512 floats; single pass, registers only.
// ---------------------------------------------------------------------------
__global__ void __launch_bounds__(256) lse_kernel(const float* __restrict__ pred,
                                                  const int* __restrict__ target) {
    const int row  = blockIdx.x * 8 + (threadIdx.x >> 5);
    const int lane = threadIdx.x & 31;
    if (row >= ROWS) return;

    const float4* p = (const float4*)(pred + (size_t)row * V_);
    float4 r[4];
#pragma unroll
    for (int k = 0; k < 4; k++) r[k] = p[k * 32 + lane];

    // max over 512
    float m = fmaxf(fmaxf(r[0].x, r[0].y), fmaxf(r[0].z, r[0].w));
#pragma unroll
    for (int k = 1; k < 4; k++)
        m = fmaxf(m, fmaxf(fmaxf(r[k].x, r[k].y), fmaxf(r[k].z, r[k].w)));
#pragma unroll
    for (int o = 16; o > 0; o >>= 1)
        m = fmaxf(m, __shfl_xor_sync(0xffffffffu, m, o));

    // sum exp(x - m)
    float s = 0.f;
#pragma unroll
    for (int k = 0; k < 4; k++)
        s += __expf(r[k].x - m) + __expf(r[k].y - m) +
             __expf(r[k].z - m) + __expf(r[k].w - m);
#pragma unroll
    for (int o = 16; o > 0; o >>= 1)
        s += __shfl_xor_sync(0xffffffffu, s, o);

    const float lse = m + __logf(s);

    const int u  = row % U1_;
    const int b  = row / (T_ * U1_);

    if (lane == 0) g_blank[row] = r[0].x - lse;   // v = 0 lives in lane 0, r[0].x

    if (u < U_) {
        const int tgt = target[b * U_ + u];       // 1..V-1
        float e = 0.f;
        bool have = false;
#pragma unroll
        for (int k = 0; k < 4; k++) {
            const int base = (k * 32 + lane) << 2;
            if (tgt >= base && tgt < base + 4) {
                have = true;
                if (tgt == base)     e = r[k].x;
                if (tgt == base + 1) e = r[k].y;
                if (tgt == base + 2) e = r[k].z;
                if (tgt == base + 3) e = r[k].w;
            }
        }
        if (have) g_emit[row] = e - lse;
    }
}

// ---------------------------------------------------------------------------
// Kernel 2: anti-diagonal wavefront alpha DP, one block per batch element.
// alpha[t][u] = logaddexp(alpha[t-1][u] + blank[t-1][u],
//                         alpha[t][u-1] + emit[t][u-1])
// Both deps of cell on diagonal n live on diagonal n-1 -> double-buffered
// SMEM exchange, one __syncthreads per diagonal, own value in a register.
// ---------------------------------------------------------------------------
__device__ __forceinline__ float log_add_exp(float a, float b) {
    const float mx = fmaxf(a, b);
    const float d  = -fabsf(a - b);
    return mx + __logf(1.f + __expf(d));
}

__global__ void __launch_bounds__(96) dp_kernel(const int* __restrict__ pred_len,
                                                const int* __restrict__ target_len) {
    const int b = blockIdx.x;
    const int u = threadIdx.x;                 // active: u <= U_

    extern __shared__ float sm[];
    float* sm_blank = sm;                      // [T_][SM_STRIDE]
    float* sm_emit  = sm + T_ * SM_STRIDE;     // [T_][SM_STRIDE]
    float* Abuf     = sm + 2 * T_ * SM_STRIDE; // [2][SM_STRIDE]

    // Stage blank/emit tables into SMEM (coalesced reads from L2).
    const float* gb = g_blank + b * T_ * U1_;
    const float* ge = g_emit  + b * T_ * U1_;
    for (int i = threadIdx.x; i < T_ * U1_; i += blockDim.x) {
        const int t  = i / U1_;
        const int uu = i - t * U1_;
        sm_blank[t * SM_STRIDE + uu] = gb[i];
        sm_emit [t * SM_STRIDE + uu] = ge[i];
    }
    __syncthreads();

    const int plast = pred_len[b] - 1;
    const int tlen  = target_len[b];

    float a_own = 0.f;

    for (int n = 0; n < T_ + U_; n++) {        // diagonals 0 .. T+U-1 (319)
        const int t = n - u;
        const bool act = (u <= U_) && (t >= 0) && (t < T_);

        float left = 0.f;
        if (act && u > 0)
            left = Abuf[((n + 1) & 1) * SM_STRIDE + (u - 1)];   // diag n-1 buffer

        if (act) {
            float v;
            if (t == 0) {
                v = (u == 0) ? 0.f : left + sm_emit[u - 1];     // row0 cumsum
            } else if (u == 0) {
                v = a_own + sm_blank[(t - 1) * SM_STRIDE];
            } else {
                const float p = a_own + sm_blank[(t - 1) * SM_STRIDE + u];
                const float q = left  + sm_emit [t * SM_STRIDE + (u - 1)];
                v = log_add_exp(p, q);
            }
            Abuf[(n & 1) * SM_STRIDE + u] = v;
            a_own = v;

            if (t == plast && u == tlen)
                g_partial[b] = -(v + sm_blank[plast * SM_STRIDE + tlen]);
        }
        __syncthreads();
    }
}

// ---------------------------------------------------------------------------
// Kernel 3: mean over batch -> d_out[0]
// ---------------------------------------------------------------------------
__global__ void finish_kernel(float* __restrict__ out) {
    if (threadIdx.x == 0) {
        float s = 0.f;
#pragma unroll
        for (int i = 0; i < B_; i++) s += g_partial[i];
        out[0] = s * (1.f / B_);
    }
}

extern "C" void kernel_launch(void* const* d_in, const int* in_sizes, int n_in,
                              void* d_out, int out_size) {
    const float* pred       = (const float*)d_in[0];  // (B,T,U+1,V) fp32
    const int*   target     = (const int*)d_in[1];    // (B,U)
    const int*   pred_len   = (const int*)d_in[2];    // (B,)
    const int*   target_len = (const int*)d_in[3];    // (B,)
    float*       out        = (float*)d_out;

    const int smem_bytes = (2 * T_ * SM_STRIDE + 2 * SM_STRIDE) * (int)sizeof(float);

    static bool attr_done = false;
    if (!attr_done) {
        cudaFuncSetAttribute(dp_kernel, cudaFuncAttributeMaxDynamicSharedMemorySize, smem_bytes);
        attr_done = true;
    }

    lse_kernel<<<ROWS / 8, 256>>>(pred, target);
    dp_kernel<<<B_, 96, smem_bytes>>>(pred_len, target_len);
    finish_kernel<<<1, 32>>>(out);
}